// round 15
// baseline (speedup 1.0000x reference)
#include <cuda_runtime.h>
#include <cuda_bf16.h>
#include <math.h>
#include <cstdint>

// Problem constants
#define NB     2048            // batch (episodes)
#define NN     26              // nodes per episode
#define FD     1024            // feature dim
#define HD     512             // hidden dim
#define E6     6               // distinct rows per episode (5 class means + query)
#define ET     (NB * E6)       // 12288 effective GEMM rows

// ---------------------------------------------------------------------------
// Static device scratch.  All bf16 hi/lo arrays use a k-interleaved layout:
// within each 16-element k-group, position 4j..4j+3 holds k = {2j,2j+1,2j+8,2j+9}.
// One LDS.64 then delivers both fragment registers of an mma operand.
// ---------------------------------------------------------------------------
__device__ __align__(16) float          g_M  [(size_t)ET * FD];  // fp32 (sim)
__device__ __align__(16) float          g_A2 [(size_t)ET * FD];  // fp32 (sim)
__device__ __align__(16) __nv_bfloat16  g_Mh [(size_t)ET * FD];
__device__ __align__(16) __nv_bfloat16  g_Ml [(size_t)ET * FD];
__device__ __align__(16) __nv_bfloat16  g_Y1h[(size_t)ET * HD];
__device__ __align__(16) __nv_bfloat16  g_Y1l[(size_t)ET * HD];
__device__ __align__(16) __nv_bfloat16  g_Y2h[(size_t)ET * HD];
__device__ __align__(16) __nv_bfloat16  g_Y2l[(size_t)ET * HD];
__device__ __align__(16) __nv_bfloat16  g_W1h[(size_t)HD * FD];
__device__ __align__(16) __nv_bfloat16  g_W1l[(size_t)HD * FD];
__device__ __align__(16) __nv_bfloat16  g_W2h[(size_t)HD * HD];
__device__ __align__(16) __nv_bfloat16  g_W2l[(size_t)HD * HD];
__device__ __align__(16) __nv_bfloat16  g_W3h[(size_t)FD * HD];
__device__ __align__(16) __nv_bfloat16  g_W3l[(size_t)FD * HD];

// permuted position of k (within its 16-group)
__device__ __forceinline__ int pperm(int km) {
    return (km < 8) ? ((km >> 1) * 4 + (km & 1))
                    : (((km - 8) >> 1) * 4 + 2 + (km & 1));
}

// ---------------------------------------------------------------------------
// PTX helpers (plain sm_103-legal: mma.sync / cp.async only)
// ---------------------------------------------------------------------------
__device__ __forceinline__ uint32_t smem_u32(const void* p) {
    uint32_t a;
    asm("{ .reg .u64 t; cvta.to.shared.u64 t, %1; cvt.u32.u64 %0, t; }"
        : "=r"(a) : "l"(p));
    return a;
}
__device__ __forceinline__ void cp_async16(uint32_t dst, const void* src) {
    asm volatile("cp.async.cg.shared.global [%0], [%1], 16;"
                 :: "r"(dst), "l"(src) : "memory");
}
__device__ __forceinline__ void cp_commit() {
    asm volatile("cp.async.commit_group;" ::: "memory");
}
template <int N>
__device__ __forceinline__ void cp_wait() {
    asm volatile("cp.async.wait_group %0;" :: "n"(N) : "memory");
}
__device__ __forceinline__ void mma16816(float* c, const uint32_t* a,
                                         const uint32_t* b) {
    asm volatile(
        "mma.sync.aligned.m16n8k16.row.col.f32.bf16.bf16.f32 "
        "{%0,%1,%2,%3}, {%4,%5,%6,%7}, {%8,%9}, {%0,%1,%2,%3};"
        : "+f"(c[0]), "+f"(c[1]), "+f"(c[2]), "+f"(c[3])
        : "r"(a[0]), "r"(a[1]), "r"(a[2]), "r"(a[3]), "r"(b[0]), "r"(b[1]));
}

// ---------------------------------------------------------------------------
// Kernel 1: per-episode class means -> g_M (fp32) + permuted split bf16
// ---------------------------------------------------------------------------
__global__ void __launch_bounds__(256) mean_kernel(const float* __restrict__ nf) {
    int b  = blockIdx.x;
    int f4 = threadIdx.x;                       // 0..255
    const float4* src = (const float4*)nf + (size_t)b * NN * (FD / 4);
    float4*        dst = (float4*)g_M    + (size_t)b * E6 * (FD / 4);
    __nv_bfloat16* dh  = g_Mh + (size_t)b * E6 * FD;
    __nv_bfloat16* dl  = g_Ml + (size_t)b * E6 * FD;

    const int k0   = f4 * 4;
    const int grp  = k0 & ~15;
    const int p01  = grp + pperm(k0 & 15);        // pos of (k0, k0+1)
    const int p23  = grp + pperm((k0 & 15) + 2);  // pos of (k0+2, k0+3)

    auto split4 = [&](size_t rowbase, float4 o) {
        __nv_bfloat162 h01, h23, l01, l23;
        h01.x = __float2bfloat16(o.x); h01.y = __float2bfloat16(o.y);
        h23.x = __float2bfloat16(o.z); h23.y = __float2bfloat16(o.w);
        l01.x = __float2bfloat16(o.x - __bfloat162float(h01.x));
        l01.y = __float2bfloat16(o.y - __bfloat162float(h01.y));
        l23.x = __float2bfloat16(o.z - __bfloat162float(h23.x));
        l23.y = __float2bfloat16(o.w - __bfloat162float(h23.y));
        *(__nv_bfloat162*)(dh + rowbase + p01) = h01;
        *(__nv_bfloat162*)(dh + rowbase + p23) = h23;
        *(__nv_bfloat162*)(dl + rowbase + p01) = l01;
        *(__nv_bfloat162*)(dl + rowbase + p23) = l23;
    };

#pragma unroll
    for (int c = 0; c < 5; c++) {
        float4 s0 = src[(c * 5 + 0) * (FD / 4) + f4];
        float4 s1 = src[(c * 5 + 1) * (FD / 4) + f4];
        float4 s2 = src[(c * 5 + 2) * (FD / 4) + f4];
        float4 s3 = src[(c * 5 + 3) * (FD / 4) + f4];
        float4 s4 = src[(c * 5 + 4) * (FD / 4) + f4];
        float4 o;
        o.x = (s0.x + s1.x + s2.x + s3.x + s4.x) / 5.0f;
        o.y = (s0.y + s1.y + s2.y + s3.y + s4.y) / 5.0f;
        o.z = (s0.z + s1.z + s2.z + s3.z + s4.z) / 5.0f;
        o.w = (s0.w + s1.w + s2.w + s3.w + s4.w) / 5.0f;
        dst[c * (FD / 4) + f4] = o;
        split4((size_t)c * FD, o);
    }
    float4 q = src[25 * (FD / 4) + f4];
    dst[5 * (FD / 4) + f4] = q;
    split4((size_t)5 * FD, q);
}

// ---------------------------------------------------------------------------
// Weight split: fp32 -> (hi, lo) bf16, permuted k layout
// ---------------------------------------------------------------------------
__global__ void __launch_bounds__(256) split_kernel(const float* __restrict__ w,
                                                    __nv_bfloat16* __restrict__ hi,
                                                    __nv_bfloat16* __restrict__ lo,
                                                    int n, int K) {
    int i = blockIdx.x * blockDim.x + threadIdx.x;
    if (i < n) {
        int k   = i % K;
        int row = i / K;
        int pi  = row * K + (k & ~15) + pperm(k & 15);
        float x = w[i];
        __nv_bfloat16 h = __float2bfloat16(x);
        hi[pi] = h;
        lo[pi] = __float2bfloat16(x - __bfloat162float(h));
    }
}

// ---------------------------------------------------------------------------
// 3-term split-bf16 HMMA GEMM, pre-split permuted operands, LDS.64 fragments:
//   acc += Ah*Wh + Al*Wh + Ah*Wl   (fp32 accumulate)
// Tile 128x128, 128 threads = 4 warps (2x2), warp tile 64x64 (m16n8k16).
// BK=16: operand tiles are 128 rows x 32B, stored CONTIGUOUS (no padding) —
// row starts mod 128 are {0,32,64,96} per 16-lane phase, so fragment LDS.64s
// are conflict-free.  4-STAGE cp.async pipeline (wait_group 2) hides global
// load latency 3 chunks deep; empty commit_groups keep FIFO semantics at tail.
// LAYER 1/2: bias+BN+leaky -> split bf16 (permuted).  LAYER 3: sigmoid^2 fp32.
// ---------------------------------------------------------------------------
#define TILEB (128 * 32)               // 4096 bytes per operand tile (BK=16)
#define BUFB  (4 * TILEB)              // Ah, Al, Wh, Wl = 16384 per stage
#define STAGES 4
#define GEMM_SMEM_BYTES (STAGES * BUFB)   // 65536

template <int K, int NCOL, int LAYER>
__global__ void __launch_bounds__(128, 2) gemm_ps(
    const __nv_bfloat16* __restrict__ Ah,
    const __nv_bfloat16* __restrict__ Al,
    const __nv_bfloat16* __restrict__ Wh,
    const __nv_bfloat16* __restrict__ Wl,
    const float* __restrict__ bias,
    const float* __restrict__ gamma,
    const float* __restrict__ beta,
    const float* __restrict__ rmean,
    const float* __restrict__ rvar)
{
    extern __shared__ __align__(16) unsigned char sbuf[];

    constexpr int NCHUNK = K / 16;

    const int tid  = threadIdx.x;
    const int wid  = tid >> 5;
    const int lane = tid & 31;
    const int wrow = wid >> 1;           // 0..1 -> 64-row block
    const int wcol = wid & 1;            // 0..1 -> 64-col block
    const int g    = lane >> 2;          // 0..7
    const int tg   = lane & 3;           // 0..3
    const int row0 = blockIdx.x * 128;
    const int col0 = blockIdx.y * 128;

    const __nv_bfloat16* srcs[4] = {Ah, Al, Wh, Wl};

    // one 128x16 bf16 chunk of each of the 4 operands -> stage buffer
    auto issue_chunk = [&](int kb, int stg) {
        const uint32_t base = smem_u32(sbuf) + (uint32_t)stg * BUFB;
#pragma unroll
        for (int i = 0; i < 8; i++) {
            const int idx  = i * 128 + tid;          // 0..1023
            const int tile = idx >> 8;               // 0..3
            const int rem  = idx & 255;
            const int r    = rem >> 1;               // 0..127
            const int s    = rem & 1;                // 16B seg (8 bf16)
            const int rb   = (tile < 2) ? row0 : col0;
            cp_async16(base + tile * TILEB + r * 32 + s * 16,
                       srcs[tile] + (size_t)(rb + r) * K + kb + s * 8);
        }
        cp_commit();
    };

    float acc[4][8][4];
#pragma unroll
    for (int mt = 0; mt < 4; mt++)
#pragma unroll
        for (int nt = 0; nt < 8; nt++)
#pragma unroll
            for (int e = 0; e < 4; e++) acc[mt][nt][e] = 0.0f;

    issue_chunk(0, 0);
    issue_chunk(16, 1);
    issue_chunk(32, 2);

    for (int cc = 0; cc < NCHUNK; cc++) {
        const int stg = cc & (STAGES - 1);
        cp_wait<STAGES - 2>();   // chunk cc landed (2 younger groups allowed)
        __syncthreads();         // visibility + WAR: all warps done with stg-1
        if (cc + STAGES - 1 < NCHUNK)
            issue_chunk((cc + STAGES - 1) * 16, (cc + STAGES - 1) & (STAGES - 1));
        else
            cp_commit();         // empty group keeps wait_group bookkeeping

        const unsigned char* pAh = sbuf + (size_t)stg * BUFB;
        const unsigned char* pAl = pAh + TILEB;
        const unsigned char* pWh = pAl + TILEB;
        const unsigned char* pWl = pWh + TILEB;

        const int koff = tg * 8;
        // ---- B fragments: one LDS.64 each for hi and lo, 8 n-tiles ----
        uint32_t bh[8][2], bl[8][2];
#pragma unroll
        for (int nt = 0; nt < 8; nt++) {
            const int ro = (wcol * 64 + nt * 8 + g) * 32 + koff;
            uint2 vh = *(const uint2*)(pWh + ro);
            uint2 vl = *(const uint2*)(pWl + ro);
            bh[nt][0] = vh.x; bh[nt][1] = vh.y;
            bl[nt][0] = vl.x; bl[nt][1] = vl.y;
        }
        // ---- A fragments per m-tile (2 LDS.64 hi + 2 lo), 3 MMA terms ----
#pragma unroll
        for (int mt = 0; mt < 4; mt++) {
            const int ro = (wrow * 64 + mt * 16 + g) * 32 + koff;
            uint2 h1 = *(const uint2*)(pAh + ro);          // row g
            uint2 h2 = *(const uint2*)(pAh + ro + 8 * 32); // row g+8
            uint2 l1 = *(const uint2*)(pAl + ro);
            uint2 l2 = *(const uint2*)(pAl + ro + 8 * 32);
            uint32_t ah[4] = {h1.x, h2.x, h1.y, h2.y};
            uint32_t al[4] = {l1.x, l2.x, l1.y, l2.y};
#pragma unroll
            for (int nt = 0; nt < 8; nt++) {
                mma16816(acc[mt][nt], ah, bh[nt]);
                mma16816(acc[mt][nt], al, bh[nt]);
                mma16816(acc[mt][nt], ah, bl[nt]);
            }
        }
    }

    // -------- fused epilogue --------
    const int er0 = row0 + wrow * 64 + g;
    const int ec0 = col0 + wcol * 64 + 2 * tg;

#pragma unroll
    for (int nt = 0; nt < 8; nt++) {
        const int h0 = ec0 + nt * 8;
        float sc0, sh0 = 0.f, sc1, sh1 = 0.f;
        if (LAYER == 3) {
            sc0 = bias[h0]; sc1 = bias[h0 + 1];
        } else {
            float s0 = gamma[h0] * rsqrtf(rvar[h0] + 1e-5f);
            float s1 = gamma[h0 + 1] * rsqrtf(rvar[h0 + 1] + 1e-5f);
            sc0 = s0; sh0 = (bias[h0] - rmean[h0]) * s0 + beta[h0];
            sc1 = s1; sh1 = (bias[h0 + 1] - rmean[h0 + 1]) * s1 + beta[h0 + 1];
        }
        const int hperm = (h0 & ~15) + pperm(h0 & 15);   // permuted pair pos
#pragma unroll
        for (int mt = 0; mt < 4; mt++) {
#pragma unroll
            for (int half = 0; half < 2; half++) {
                int r = er0 + mt * 16 + half * 8;
                float v0 = acc[mt][nt][half * 2 + 0];
                float v1 = acc[mt][nt][half * 2 + 1];
                if (LAYER == 3) {
                    float y0 = v0 + sc0, y1 = v1 + sc1;
                    float q0 = 1.0f / (1.0f + expf(-y0));
                    float q1 = 1.0f / (1.0f + expf(-y1));
                    float2 o; o.x = q0 * q0; o.y = q1 * q1;
                    *(float2*)(g_A2 + (size_t)r * NCOL + h0) = o;
                } else {
                    float y0 = v0 * sc0 + sh0;
                    float y1 = v1 * sc1 + sh1;
                    y0 = (y0 > 0.0f) ? y0 : 0.01f * y0;
                    y1 = (y1 > 0.0f) ? y1 : 0.01f * y1;
                    __nv_bfloat16* Ch = (LAYER == 1) ? g_Y1h : g_Y2h;
                    __nv_bfloat16* Cl = (LAYER == 1) ? g_Y1l : g_Y2l;
                    __nv_bfloat162 hp, lp;
                    hp.x = __float2bfloat16(y0);
                    hp.y = __float2bfloat16(y1);
                    lp.x = __float2bfloat16(y0 - __bfloat162float(hp.x));
                    lp.y = __float2bfloat16(y1 - __bfloat162float(hp.y));
                    *(__nv_bfloat162*)(Ch + (size_t)r * NCOL + hperm) = hp;
                    *(__nv_bfloat162*)(Cl + (size_t)r * NCOL + hperm) = lp;
                }
            }
        }
    }
}

// ---------------------------------------------------------------------------
// Kernel: per-episode 6x6 cosine similarity, ONE WARP PER EPISODE (proven).
// ---------------------------------------------------------------------------
__global__ void __launch_bounds__(256) sim_kernel(float* __restrict__ out) {
    const int tid  = threadIdx.x;
    const int wid  = tid >> 5;
    const int lane = tid & 31;
    const int ep   = blockIdx.x * 8 + wid;      // episode

    __shared__ float sred[8][57];
    __shared__ float ssim[8][36];

    const float* Mb = g_M  + (size_t)ep * E6 * FD;
    const float* Ab = g_A2 + (size_t)ep * E6 * FD;

    float d[21], n2[36];
#pragma unroll
    for (int t = 0; t < 21; t++) d[t] = 0.0f;
#pragma unroll
    for (int t = 0; t < 36; t++) n2[t] = 0.0f;

    for (int it = 0; it < FD / 32; it++) {
        const int f = lane + it * 32;
        float x[6], a[6];
#pragma unroll
        for (int i = 0; i < 6; i++) {
            x[i] = Mb[i * FD + f];
            a[i] = Ab[i * FD + f];
        }
        float p[6], q[6];
#pragma unroll
        for (int i = 0; i < 6; i++) {
            p[i] = a[i] * x[i];
            q[i] = p[i] * x[i];
        }
        {
            int t = 0;
#pragma unroll
            for (int i = 0; i < 6; i++)
#pragma unroll
                for (int j = i; j < 6; j++) { d[t] += p[i] * p[j]; t++; }
        }
#pragma unroll
        for (int i = 0; i < 6; i++)
#pragma unroll
            for (int j = 0; j < 6; j++)
                n2[i * 6 + j] += q[i] * a[j];
    }

    // warp butterfly reduce (all lanes end with the full sums)
#pragma unroll
    for (int off = 16; off > 0; off >>= 1) {
#pragma unroll
        for (int t = 0; t < 21; t++)
            d[t] += __shfl_xor_sync(0xffffffffu, d[t], off);
#pragma unroll
        for (int t = 0; t < 36; t++)
            n2[t] += __shfl_xor_sync(0xffffffffu, n2[t], off);
    }

    // scatter to smem with static register indexing
#pragma unroll
    for (int t = 0; t < 21; t++)
        if (lane == t) sred[wid][t] = d[t];
#pragma unroll
    for (int t = 0; t < 32; t++)
        if (lane == t) sred[wid][21 + t] = n2[t];
#pragma unroll
    for (int t = 32; t < 36; t++)
        if (lane == t - 32 + 8) sred[wid][21 + t] = n2[t];   // lanes 8..11
    __syncwarp();

    // all 36 ordered pairs (lanes 0..3 handle two pairs)
    for (int t = lane; t < 36; t += 32) {
        int i = t / 6, j = t % 6;
        int lo = i < j ? i : j;
        int hi = i < j ? j : i;
        int tidx = 6 * lo - (lo * (lo - 1)) / 2 + (hi - lo);
        float dd  = sred[wid][tidx];
        float nij = sred[wid][21 + i * 6 + j];
        float nji = sred[wid][21 + j * 6 + i];
        ssim[wid][t] = dd / (sqrtf(nij) * sqrtf(nji));
    }
    __syncwarp();

    size_t base = (size_t)ep * (2 * NN * NN);
    for (int idx = lane; idx < 2 * NN * NN; idx += 32) {
        int s  = idx / (NN * NN);
        int rr = idx - s * (NN * NN);
        int i  = rr / NN;
        int j  = rr - i * NN;
        int ci = (i < 25) ? (i / 5) : 5;
        int cj = (j < 25) ? (j / 5) : 5;
        float v = ssim[wid][ci * 6 + cj];
        if (s) v = 1.0f - v;
        out[base + idx] = fminf(fmaxf(v, 0.0f), 1.0f);
    }
}

// ---------------------------------------------------------------------------
// Launch (graph-capturable)
// ---------------------------------------------------------------------------
extern "C" void kernel_launch(void* const* d_in, const int* in_sizes, int n_in,
                              void* d_out, int out_size) {
    const float* nf  = (const float*)d_in[0];
    const float* w1  = (const float*)d_in[1];
    const float* b1  = (const float*)d_in[2];
    const float* g1  = (const float*)d_in[3];
    const float* be1 = (const float*)d_in[4];
    const float* m1  = (const float*)d_in[5];
    const float* v1  = (const float*)d_in[6];
    const float* w2  = (const float*)d_in[7];
    const float* b2  = (const float*)d_in[8];
    const float* g2  = (const float*)d_in[9];
    const float* be2 = (const float*)d_in[10];
    const float* m2  = (const float*)d_in[11];
    const float* v2  = (const float*)d_in[12];
    const float* w3  = (const float*)d_in[13];
    const float* b3  = (const float*)d_in[14];
    float* out = (float*)d_out;

    __nv_bfloat16 *pMh, *pMl, *pY1h, *pY1l, *pY2h, *pY2l;
    __nv_bfloat16 *pW1h, *pW1l, *pW2h, *pW2l, *pW3h, *pW3l;
    cudaGetSymbolAddress((void**)&pMh,  g_Mh);
    cudaGetSymbolAddress((void**)&pMl,  g_Ml);
    cudaGetSymbolAddress((void**)&pY1h, g_Y1h);
    cudaGetSymbolAddress((void**)&pY1l, g_Y1l);
    cudaGetSymbolAddress((void**)&pY2h, g_Y2h);
    cudaGetSymbolAddress((void**)&pY2l, g_Y2l);
    cudaGetSymbolAddress((void**)&pW1h, g_W1h);
    cudaGetSymbolAddress((void**)&pW1l, g_W1l);
    cudaGetSymbolAddress((void**)&pW2h, g_W2h);
    cudaGetSymbolAddress((void**)&pW2l, g_W2l);
    cudaGetSymbolAddress((void**)&pW3h, g_W3h);
    cudaGetSymbolAddress((void**)&pW3l, g_W3l);

    cudaFuncSetAttribute(gemm_ps<FD, HD, 1>,
                         cudaFuncAttributeMaxDynamicSharedMemorySize,
                         GEMM_SMEM_BYTES);
    cudaFuncSetAttribute(gemm_ps<HD, HD, 2>,
                         cudaFuncAttributeMaxDynamicSharedMemorySize,
                         GEMM_SMEM_BYTES);
    cudaFuncSetAttribute(gemm_ps<HD, FD, 3>,
                         cudaFuncAttributeMaxDynamicSharedMemorySize,
                         GEMM_SMEM_BYTES);

    // weight splits (fp32 -> hi/lo bf16, permuted layout)
    split_kernel<<<(HD * FD + 255) / 256, 256>>>(w1, pW1h, pW1l, HD * FD, FD);
    split_kernel<<<(HD * HD + 255) / 256, 256>>>(w2, pW2h, pW2l, HD * HD, HD);
    split_kernel<<<(FD * HD + 255) / 256, 256>>>(w3, pW3h, pW3l, FD * HD, HD);

    // class means (fp32 + permuted split bf16)
    mean_kernel<<<NB, 256>>>(nf);

    // Y1 = leaky(bn1(M @ w1^T + b1))
    gemm_ps<FD, HD, 1><<<dim3(ET / 128, HD / 128), 128, GEMM_SMEM_BYTES>>>(
        pMh, pMl, pW1h, pW1l, b1, g1, be1, m1, v1);
    // Y2 = leaky(bn2(Y1 @ w2^T + b2))
    gemm_ps<HD, HD, 2><<<dim3(ET / 128, HD / 128), 128, GEMM_SMEM_BYTES>>>(
        pY1h, pY1l, pW2h, pW2l, b2, g2, be2, m2, v2);
    // A2 = sigmoid(Y2 @ w3^T + b3)^2
    gemm_ps<HD, FD, 3><<<dim3(ET / 128, FD / 128), 128, GEMM_SMEM_BYTES>>>(
        pY2h, pY2l, pW3h, pW3l, b3, nullptr, nullptr, nullptr, nullptr);

    // per-episode 6x6 cosine sim -> broadcast [2,26,26]  (one warp/episode)
    sim_kernel<<<NB / 8, 256>>>(out);
}

// round 16
// speedup vs baseline: 1.0393x; 1.0393x over previous
#include <cuda_runtime.h>
#include <cuda_bf16.h>
#include <math.h>
#include <cstdint>

// Problem constants
#define NB     2048            // batch (episodes)
#define NN     26              // nodes per episode
#define FD     1024            // feature dim
#define HD     512             // hidden dim
#define E6     6               // distinct rows per episode (5 class means + query)
#define ET     (NB * E6)       // 12288 effective GEMM rows

// ---------------------------------------------------------------------------
// Static device scratch.  All bf16 hi/lo arrays use a k-interleaved layout:
// within each 16-element k-group, position 4j..4j+3 holds k = {2j,2j+1,2j+8,2j+9}.
// One LDS.64 then delivers both fragment registers of an mma operand.
// ---------------------------------------------------------------------------
__device__ __align__(16) float          g_M  [(size_t)ET * FD];  // fp32 (sim)
__device__ __align__(16) float          g_A2 [(size_t)ET * FD];  // fp32 (sim)
__device__ __align__(16) __nv_bfloat16  g_Mh [(size_t)ET * FD];
__device__ __align__(16) __nv_bfloat16  g_Ml [(size_t)ET * FD];
__device__ __align__(16) __nv_bfloat16  g_Y1h[(size_t)ET * HD];
__device__ __align__(16) __nv_bfloat16  g_Y1l[(size_t)ET * HD];
__device__ __align__(16) __nv_bfloat16  g_Y2h[(size_t)ET * HD];
__device__ __align__(16) __nv_bfloat16  g_Y2l[(size_t)ET * HD];
__device__ __align__(16) __nv_bfloat16  g_W1h[(size_t)HD * FD];
__device__ __align__(16) __nv_bfloat16  g_W1l[(size_t)HD * FD];
__device__ __align__(16) __nv_bfloat16  g_W2h[(size_t)HD * HD];
__device__ __align__(16) __nv_bfloat16  g_W2l[(size_t)HD * HD];
__device__ __align__(16) __nv_bfloat16  g_W3h[(size_t)FD * HD];
__device__ __align__(16) __nv_bfloat16  g_W3l[(size_t)FD * HD];

// permuted position of k (within its 16-group)
__device__ __forceinline__ int pperm(int km) {
    return (km < 8) ? ((km >> 1) * 4 + (km & 1))
                    : (((km - 8) >> 1) * 4 + 2 + (km & 1));
}

// ---------------------------------------------------------------------------
// PTX helpers (plain sm_103-legal: mma.sync / cp.async only)
// ---------------------------------------------------------------------------
__device__ __forceinline__ uint32_t smem_u32(const void* p) {
    uint32_t a;
    asm("{ .reg .u64 t; cvta.to.shared.u64 t, %1; cvt.u32.u64 %0, t; }"
        : "=r"(a) : "l"(p));
    return a;
}
__device__ __forceinline__ void cp_async16(uint32_t dst, const void* src) {
    asm volatile("cp.async.cg.shared.global [%0], [%1], 16;"
                 :: "r"(dst), "l"(src) : "memory");
}
__device__ __forceinline__ void cp_commit() {
    asm volatile("cp.async.commit_group;" ::: "memory");
}
template <int N>
__device__ __forceinline__ void cp_wait() {
    asm volatile("cp.async.wait_group %0;" :: "n"(N) : "memory");
}
__device__ __forceinline__ void mma16816(float* c, const uint32_t* a,
                                         const uint32_t* b) {
    asm volatile(
        "mma.sync.aligned.m16n8k16.row.col.f32.bf16.bf16.f32 "
        "{%0,%1,%2,%3}, {%4,%5,%6,%7}, {%8,%9}, {%0,%1,%2,%3};"
        : "+f"(c[0]), "+f"(c[1]), "+f"(c[2]), "+f"(c[3])
        : "r"(a[0]), "r"(a[1]), "r"(a[2]), "r"(a[3]), "r"(b[0]), "r"(b[1]));
}

// ---------------------------------------------------------------------------
// Kernel 1: per-episode class means -> g_M (fp32) + permuted split bf16
// ---------------------------------------------------------------------------
__global__ void __launch_bounds__(256) mean_kernel(const float* __restrict__ nf) {
    int b  = blockIdx.x;
    int f4 = threadIdx.x;                       // 0..255
    const float4* src = (const float4*)nf + (size_t)b * NN * (FD / 4);
    float4*        dst = (float4*)g_M    + (size_t)b * E6 * (FD / 4);
    __nv_bfloat16* dh  = g_Mh + (size_t)b * E6 * FD;
    __nv_bfloat16* dl  = g_Ml + (size_t)b * E6 * FD;

    const int k0   = f4 * 4;
    const int grp  = k0 & ~15;
    const int p01  = grp + pperm(k0 & 15);        // pos of (k0, k0+1)
    const int p23  = grp + pperm((k0 & 15) + 2);  // pos of (k0+2, k0+3)

    auto split4 = [&](size_t rowbase, float4 o) {
        __nv_bfloat162 h01, h23, l01, l23;
        h01.x = __float2bfloat16(o.x); h01.y = __float2bfloat16(o.y);
        h23.x = __float2bfloat16(o.z); h23.y = __float2bfloat16(o.w);
        l01.x = __float2bfloat16(o.x - __bfloat162float(h01.x));
        l01.y = __float2bfloat16(o.y - __bfloat162float(h01.y));
        l23.x = __float2bfloat16(o.z - __bfloat162float(h23.x));
        l23.y = __float2bfloat16(o.w - __bfloat162float(h23.y));
        *(__nv_bfloat162*)(dh + rowbase + p01) = h01;
        *(__nv_bfloat162*)(dh + rowbase + p23) = h23;
        *(__nv_bfloat162*)(dl + rowbase + p01) = l01;
        *(__nv_bfloat162*)(dl + rowbase + p23) = l23;
    };

#pragma unroll
    for (int c = 0; c < 5; c++) {
        float4 s0 = src[(c * 5 + 0) * (FD / 4) + f4];
        float4 s1 = src[(c * 5 + 1) * (FD / 4) + f4];
        float4 s2 = src[(c * 5 + 2) * (FD / 4) + f4];
        float4 s3 = src[(c * 5 + 3) * (FD / 4) + f4];
        float4 s4 = src[(c * 5 + 4) * (FD / 4) + f4];
        float4 o;
        o.x = (s0.x + s1.x + s2.x + s3.x + s4.x) / 5.0f;
        o.y = (s0.y + s1.y + s2.y + s3.y + s4.y) / 5.0f;
        o.z = (s0.z + s1.z + s2.z + s3.z + s4.z) / 5.0f;
        o.w = (s0.w + s1.w + s2.w + s3.w + s4.w) / 5.0f;
        dst[c * (FD / 4) + f4] = o;
        split4((size_t)c * FD, o);
    }
    float4 q = src[25 * (FD / 4) + f4];
    dst[5 * (FD / 4) + f4] = q;
    split4((size_t)5 * FD, q);
}

// ---------------------------------------------------------------------------
// Weight split: fp32 -> (hi, lo) bf16, permuted k layout
// ---------------------------------------------------------------------------
__global__ void __launch_bounds__(256) split_kernel(const float* __restrict__ w,
                                                    __nv_bfloat16* __restrict__ hi,
                                                    __nv_bfloat16* __restrict__ lo,
                                                    int n, int K) {
    int i = blockIdx.x * blockDim.x + threadIdx.x;
    if (i < n) {
        int k   = i % K;
        int row = i / K;
        int pi  = row * K + (k & ~15) + pperm(k & 15);
        float x = w[i];
        __nv_bfloat16 h = __float2bfloat16(x);
        hi[pi] = h;
        lo[pi] = __float2bfloat16(x - __bfloat162float(h));
    }
}

// ---------------------------------------------------------------------------
// 3-term split-bf16 HMMA GEMM, pre-split permuted operands, LDS.64 fragments:
//   acc += Ah*Wh + Al*Wh + Ah*Wl   (fp32 accumulate)
// Tile 128x128, 128 threads = 4 warps (2x2), warp tile 64x64 (m16n8k16).
// BK=32, 96B-padded rows (conflict-free LDS.64), double-buffered, 1 sync per
// chunk — the proven R14 shape.  NEW: TERM-MAJOR MMA ordering — all fragments
// for a ks step are loaded first, then the 3 split terms are issued as
// separate passes over (mt, nt), so consecutive updates of the same
// accumulator are 32 MMAs apart (HMMA RAW latency fully hidden).
// LAYER 1/2: bias+BN+leaky -> split bf16 (permuted).  LAYER 3: sigmoid^2 fp32.
// ---------------------------------------------------------------------------
#define RPADB 96                       // bytes per smem row (64 data + 32 pad)
#define TILEB (128 * RPADB)            // 12288 bytes per tile
#define BUFB  (4 * TILEB)              // Ah, Al, Wh, Wl
#define GEMM_SMEM_BYTES (2 * BUFB)     // 98304

template <int K, int NCOL, int LAYER>
__global__ void __launch_bounds__(128, 2) gemm_ps(
    const __nv_bfloat16* __restrict__ Ah,
    const __nv_bfloat16* __restrict__ Al,
    const __nv_bfloat16* __restrict__ Wh,
    const __nv_bfloat16* __restrict__ Wl,
    const float* __restrict__ bias,
    const float* __restrict__ gamma,
    const float* __restrict__ beta,
    const float* __restrict__ rmean,
    const float* __restrict__ rvar)
{
    extern __shared__ __align__(16) unsigned char sbuf[];

    constexpr int NCHUNK = K / 32;

    const int tid  = threadIdx.x;
    const int wid  = tid >> 5;
    const int lane = tid & 31;
    const int wrow = wid >> 1;           // 0..1 -> 64-row block
    const int wcol = wid & 1;            // 0..1 -> 64-col block
    const int g    = lane >> 2;          // 0..7
    const int tg   = lane & 3;           // 0..3
    const int row0 = blockIdx.x * 128;
    const int col0 = blockIdx.y * 128;

    const __nv_bfloat16* srcs[4] = {Ah, Al, Wh, Wl};

    auto issue_chunk = [&](int kb, int buf) {
        const uint32_t base = smem_u32(sbuf) + (uint32_t)buf * BUFB;
#pragma unroll
        for (int i = 0; i < 16; i++) {
            const int idx  = i * 128 + tid;          // 0..2047
            const int tile = idx >> 9;               // 0..3
            const int rem  = idx & 511;
            const int r    = rem >> 2;               // 0..127
            const int s    = rem & 3;                // 16B seg (8 bf16)
            const int rb   = (tile < 2) ? row0 : col0;
            cp_async16(base + tile * TILEB + r * RPADB + s * 16,
                       srcs[tile] + (size_t)(rb + r) * K + kb + s * 8);
        }
        cp_commit();
    };

    float acc[4][8][4];
#pragma unroll
    for (int mt = 0; mt < 4; mt++)
#pragma unroll
        for (int nt = 0; nt < 8; nt++)
#pragma unroll
            for (int e = 0; e < 4; e++) acc[mt][nt][e] = 0.0f;

    issue_chunk(0, 0);

    for (int cc = 0; cc < NCHUNK; cc++) {
        const int buf = cc & 1;
        cp_wait<0>();          // only this chunk's group is outstanding
        __syncthreads();       // data visible + prev compute of buf^1 done
        if (cc + 1 < NCHUNK) issue_chunk((cc + 1) * 32, buf ^ 1);

        const unsigned char* pAh = sbuf + (size_t)buf * BUFB;
        const unsigned char* pAl = pAh + TILEB;
        const unsigned char* pWh = pAl + TILEB;
        const unsigned char* pWl = pWh + TILEB;

#pragma unroll
        for (int ks = 0; ks < 2; ks++) {
            const int koff = ks * 32 + tg * 8;

            // ---- load ALL fragments for this ks step first ----
            uint32_t bh[8][2], bl[8][2];
#pragma unroll
            for (int nt = 0; nt < 8; nt++) {
                const int ro = (wcol * 64 + nt * 8 + g) * RPADB + koff;
                uint2 vh = *(const uint2*)(pWh + ro);
                uint2 vl = *(const uint2*)(pWl + ro);
                bh[nt][0] = vh.x; bh[nt][1] = vh.y;
                bl[nt][0] = vl.x; bl[nt][1] = vl.y;
            }
            uint32_t ah[4][4], al[4][4];
#pragma unroll
            for (int mt = 0; mt < 4; mt++) {
                const int ro = (wrow * 64 + mt * 16 + g) * RPADB + koff;
                uint2 h1 = *(const uint2*)(pAh + ro);             // row g
                uint2 h2 = *(const uint2*)(pAh + ro + 8 * RPADB); // row g+8
                uint2 l1 = *(const uint2*)(pAl + ro);
                uint2 l2 = *(const uint2*)(pAl + ro + 8 * RPADB);
                ah[mt][0] = h1.x; ah[mt][1] = h2.x;
                ah[mt][2] = h1.y; ah[mt][3] = h2.y;
                al[mt][0] = l1.x; al[mt][1] = l2.x;
                al[mt][2] = l1.y; al[mt][3] = l2.y;
            }

            // ---- term-major MMA issue: same-acc updates 32 apart ----
#pragma unroll
            for (int mt = 0; mt < 4; mt++)
#pragma unroll
                for (int nt = 0; nt < 8; nt++)
                    mma16816(acc[mt][nt], ah[mt], bh[nt]);
#pragma unroll
            for (int mt = 0; mt < 4; mt++)
#pragma unroll
                for (int nt = 0; nt < 8; nt++)
                    mma16816(acc[mt][nt], al[mt], bh[nt]);
#pragma unroll
            for (int mt = 0; mt < 4; mt++)
#pragma unroll
                for (int nt = 0; nt < 8; nt++)
                    mma16816(acc[mt][nt], ah[mt], bl[nt]);
        }
    }

    // -------- fused epilogue --------
    const int er0 = row0 + wrow * 64 + g;
    const int ec0 = col0 + wcol * 64 + 2 * tg;

#pragma unroll
    for (int nt = 0; nt < 8; nt++) {
        const int h0 = ec0 + nt * 8;
        float sc0, sh0 = 0.f, sc1, sh1 = 0.f;
        if (LAYER == 3) {
            sc0 = bias[h0]; sc1 = bias[h0 + 1];
        } else {
            float s0 = gamma[h0] * rsqrtf(rvar[h0] + 1e-5f);
            float s1 = gamma[h0 + 1] * rsqrtf(rvar[h0 + 1] + 1e-5f);
            sc0 = s0; sh0 = (bias[h0] - rmean[h0]) * s0 + beta[h0];
            sc1 = s1; sh1 = (bias[h0 + 1] - rmean[h0 + 1]) * s1 + beta[h0 + 1];
        }
        const int hperm = (h0 & ~15) + pperm(h0 & 15);   // permuted pair pos
#pragma unroll
        for (int mt = 0; mt < 4; mt++) {
#pragma unroll
            for (int half = 0; half < 2; half++) {
                int r = er0 + mt * 16 + half * 8;
                float v0 = acc[mt][nt][half * 2 + 0];
                float v1 = acc[mt][nt][half * 2 + 1];
                if (LAYER == 3) {
                    float y0 = v0 + sc0, y1 = v1 + sc1;
                    float q0 = 1.0f / (1.0f + expf(-y0));
                    float q1 = 1.0f / (1.0f + expf(-y1));
                    float2 o; o.x = q0 * q0; o.y = q1 * q1;
                    *(float2*)(g_A2 + (size_t)r * NCOL + h0) = o;
                } else {
                    float y0 = v0 * sc0 + sh0;
                    float y1 = v1 * sc1 + sh1;
                    y0 = (y0 > 0.0f) ? y0 : 0.01f * y0;
                    y1 = (y1 > 0.0f) ? y1 : 0.01f * y1;
                    __nv_bfloat16* Ch = (LAYER == 1) ? g_Y1h : g_Y2h;
                    __nv_bfloat16* Cl = (LAYER == 1) ? g_Y1l : g_Y2l;
                    __nv_bfloat162 hp, lp;
                    hp.x = __float2bfloat16(y0);
                    hp.y = __float2bfloat16(y1);
                    lp.x = __float2bfloat16(y0 - __bfloat162float(hp.x));
                    lp.y = __float2bfloat16(y1 - __bfloat162float(hp.y));
                    *(__nv_bfloat162*)(Ch + (size_t)r * NCOL + hperm) = hp;
                    *(__nv_bfloat162*)(Cl + (size_t)r * NCOL + hperm) = lp;
                }
            }
        }
    }
}

// ---------------------------------------------------------------------------
// Kernel: per-episode 6x6 cosine similarity, ONE WARP PER EPISODE (proven).
// ---------------------------------------------------------------------------
__global__ void __launch_bounds__(256) sim_kernel(float* __restrict__ out) {
    const int tid  = threadIdx.x;
    const int wid  = tid >> 5;
    const int lane = tid & 31;
    const int ep   = blockIdx.x * 8 + wid;      // episode

    __shared__ float sred[8][57];
    __shared__ float ssim[8][36];

    const float* Mb = g_M  + (size_t)ep * E6 * FD;
    const float* Ab = g_A2 + (size_t)ep * E6 * FD;

    float d[21], n2[36];
#pragma unroll
    for (int t = 0; t < 21; t++) d[t] = 0.0f;
#pragma unroll
    for (int t = 0; t < 36; t++) n2[t] = 0.0f;

    for (int it = 0; it < FD / 32; it++) {
        const int f = lane + it * 32;
        float x[6], a[6];
#pragma unroll
        for (int i = 0; i < 6; i++) {
            x[i] = Mb[i * FD + f];
            a[i] = Ab[i * FD + f];
        }
        float p[6], q[6];
#pragma unroll
        for (int i = 0; i < 6; i++) {
            p[i] = a[i] * x[i];
            q[i] = p[i] * x[i];
        }
        {
            int t = 0;
#pragma unroll
            for (int i = 0; i < 6; i++)
#pragma unroll
                for (int j = i; j < 6; j++) { d[t] += p[i] * p[j]; t++; }
        }
#pragma unroll
        for (int i = 0; i < 6; i++)
#pragma unroll
            for (int j = 0; j < 6; j++)
                n2[i * 6 + j] += q[i] * a[j];
    }

    // warp butterfly reduce (all lanes end with the full sums)
#pragma unroll
    for (int off = 16; off > 0; off >>= 1) {
#pragma unroll
        for (int t = 0; t < 21; t++)
            d[t] += __shfl_xor_sync(0xffffffffu, d[t], off);
#pragma unroll
        for (int t = 0; t < 36; t++)
            n2[t] += __shfl_xor_sync(0xffffffffu, n2[t], off);
    }

    // scatter to smem with static register indexing
#pragma unroll
    for (int t = 0; t < 21; t++)
        if (lane == t) sred[wid][t] = d[t];
#pragma unroll
    for (int t = 0; t < 32; t++)
        if (lane == t) sred[wid][21 + t] = n2[t];
#pragma unroll
    for (int t = 32; t < 36; t++)
        if (lane == t - 32 + 8) sred[wid][21 + t] = n2[t];   // lanes 8..11
    __syncwarp();

    // all 36 ordered pairs (lanes 0..3 handle two pairs)
    for (int t = lane; t < 36; t += 32) {
        int i = t / 6, j = t % 6;
        int lo = i < j ? i : j;
        int hi = i < j ? j : i;
        int tidx = 6 * lo - (lo * (lo - 1)) / 2 + (hi - lo);
        float dd  = sred[wid][tidx];
        float nij = sred[wid][21 + i * 6 + j];
        float nji = sred[wid][21 + j * 6 + i];
        ssim[wid][t] = dd / (sqrtf(nij) * sqrtf(nji));
    }
    __syncwarp();

    size_t base = (size_t)ep * (2 * NN * NN);
    for (int idx = lane; idx < 2 * NN * NN; idx += 32) {
        int s  = idx / (NN * NN);
        int rr = idx - s * (NN * NN);
        int i  = rr / NN;
        int j  = rr - i * NN;
        int ci = (i < 25) ? (i / 5) : 5;
        int cj = (j < 25) ? (j / 5) : 5;
        float v = ssim[wid][ci * 6 + cj];
        if (s) v = 1.0f - v;
        out[base + idx] = fminf(fmaxf(v, 0.0f), 1.0f);
    }
}

// ---------------------------------------------------------------------------
// Launch (graph-capturable)
// ---------------------------------------------------------------------------
extern "C" void kernel_launch(void* const* d_in, const int* in_sizes, int n_in,
                              void* d_out, int out_size) {
    const float* nf  = (const float*)d_in[0];
    const float* w1  = (const float*)d_in[1];
    const float* b1  = (const float*)d_in[2];
    const float* g1  = (const float*)d_in[3];
    const float* be1 = (const float*)d_in[4];
    const float* m1  = (const float*)d_in[5];
    const float* v1  = (const float*)d_in[6];
    const float* w2  = (const float*)d_in[7];
    const float* b2  = (const float*)d_in[8];
    const float* g2  = (const float*)d_in[9];
    const float* be2 = (const float*)d_in[10];
    const float* m2  = (const float*)d_in[11];
    const float* v2  = (const float*)d_in[12];
    const float* w3  = (const float*)d_in[13];
    const float* b3  = (const float*)d_in[14];
    float* out = (float*)d_out;

    __nv_bfloat16 *pMh, *pMl, *pY1h, *pY1l, *pY2h, *pY2l;
    __nv_bfloat16 *pW1h, *pW1l, *pW2h, *pW2l, *pW3h, *pW3l;
    cudaGetSymbolAddress((void**)&pMh,  g_Mh);
    cudaGetSymbolAddress((void**)&pMl,  g_Ml);
    cudaGetSymbolAddress((void**)&pY1h, g_Y1h);
    cudaGetSymbolAddress((void**)&pY1l, g_Y1l);
    cudaGetSymbolAddress((void**)&pY2h, g_Y2h);
    cudaGetSymbolAddress((void**)&pY2l, g_Y2l);
    cudaGetSymbolAddress((void**)&pW1h, g_W1h);
    cudaGetSymbolAddress((void**)&pW1l, g_W1l);
    cudaGetSymbolAddress((void**)&pW2h, g_W2h);
    cudaGetSymbolAddress((void**)&pW2l, g_W2l);
    cudaGetSymbolAddress((void**)&pW3h, g_W3h);
    cudaGetSymbolAddress((void**)&pW3l, g_W3l);

    cudaFuncSetAttribute(gemm_ps<FD, HD, 1>,
                         cudaFuncAttributeMaxDynamicSharedMemorySize,
                         GEMM_SMEM_BYTES);
    cudaFuncSetAttribute(gemm_ps<HD, HD, 2>,
                         cudaFuncAttributeMaxDynamicSharedMemorySize,
                         GEMM_SMEM_BYTES);
    cudaFuncSetAttribute(gemm_ps<HD, FD, 3>,
                         cudaFuncAttributeMaxDynamicSharedMemorySize,
                         GEMM_SMEM_BYTES);

    // weight splits (fp32 -> hi/lo bf16, permuted layout)
    split_kernel<<<(HD * FD + 255) / 256, 256>>>(w1, pW1h, pW1l, HD * FD, FD);
    split_kernel<<<(HD * HD + 255) / 256, 256>>>(w2, pW2h, pW2l, HD * HD, HD);
    split_kernel<<<(FD * HD + 255) / 256, 256>>>(w3, pW3h, pW3l, FD * HD, HD);

    // class means (fp32 + permuted split bf16)
    mean_kernel<<<NB, 256>>>(nf);

    // Y1 = leaky(bn1(M @ w1^T + b1))
    gemm_ps<FD, HD, 1><<<dim3(ET / 128, HD / 128), 128, GEMM_SMEM_BYTES>>>(
        pMh, pMl, pW1h, pW1l, b1, g1, be1, m1, v1);
    // Y2 = leaky(bn2(Y1 @ w2^T + b2))
    gemm_ps<HD, HD, 2><<<dim3(ET / 128, HD / 128), 128, GEMM_SMEM_BYTES>>>(
        pY1h, pY1l, pW2h, pW2l, b2, g2, be2, m2, v2);
    // A2 = sigmoid(Y2 @ w3^T + b3)^2
    gemm_ps<HD, FD, 3><<<dim3(ET / 128, FD / 128), 128, GEMM_SMEM_BYTES>>>(
        pY2h, pY2l, pW3h, pW3l, b3, nullptr, nullptr, nullptr, nullptr);

    // per-episode 6x6 cosine sim -> broadcast [2,26,26]  (one warp/episode)
    sim_kernel<<<NB / 8, 256>>>(out);
}

// round 17
// speedup vs baseline: 1.1380x; 1.0949x over previous
#include <cuda_runtime.h>
#include <cuda_bf16.h>
#include <math.h>
#include <cstdint>

// Problem constants
#define NB     2048            // batch (episodes)
#define NN     26              // nodes per episode
#define FD     1024            // feature dim
#define HD     512             // hidden dim
#define E6     6               // distinct rows per episode (5 class means + query)
#define ET     (NB * E6)       // 12288 effective GEMM rows

// ---------------------------------------------------------------------------
// Static device scratch.  bf16 hi/lo arrays use a 32-wide k-interleaved
// layout: within each 32-element k-group, element k sits at
//   pos = tg*8 + ks*4 + hi8*2 + parity
// where ks=k>>4, r=k&15, tg=(r&7)>>1, hi8=r>>3, parity=r&1.
// One LDS.128 at (row*64 + tg*16) then yields a thread's mma fragment regs
// for BOTH k16 halves of a 32-K chunk.
// ---------------------------------------------------------------------------
__device__ __align__(16) float          g_M  [(size_t)ET * FD];  // fp32 (sim)
__device__ __align__(16) float          g_A2 [(size_t)ET * FD];  // fp32 (sim)
__device__ __align__(16) __nv_bfloat16  g_Mh [(size_t)ET * FD];
__device__ __align__(16) __nv_bfloat16  g_Ml [(size_t)ET * FD];
__device__ __align__(16) __nv_bfloat16  g_Y1h[(size_t)ET * HD];
__device__ __align__(16) __nv_bfloat16  g_Y1l[(size_t)ET * HD];
__device__ __align__(16) __nv_bfloat16  g_Y2h[(size_t)ET * HD];
__device__ __align__(16) __nv_bfloat16  g_Y2l[(size_t)ET * HD];
__device__ __align__(16) __nv_bfloat16  g_W1h[(size_t)HD * FD];
__device__ __align__(16) __nv_bfloat16  g_W1l[(size_t)HD * FD];
__device__ __align__(16) __nv_bfloat16  g_W2h[(size_t)HD * HD];
__device__ __align__(16) __nv_bfloat16  g_W2l[(size_t)HD * HD];
__device__ __align__(16) __nv_bfloat16  g_W3h[(size_t)FD * HD];
__device__ __align__(16) __nv_bfloat16  g_W3l[(size_t)FD * HD];

// permuted position of k within its 32-group
__device__ __forceinline__ int pperm32(int k) {
    int ks = k >> 4;
    int r  = k & 15;
    return ((r & 7) >> 1) * 8 + ks * 4 + (r >> 3) * 2 + (r & 1);
}

// ---------------------------------------------------------------------------
// PTX helpers (plain sm_103-legal: mma.sync / cp.async only)
// ---------------------------------------------------------------------------
__device__ __forceinline__ uint32_t smem_u32(const void* p) {
    uint32_t a;
    asm("{ .reg .u64 t; cvta.to.shared.u64 t, %1; cvt.u32.u64 %0, t; }"
        : "=r"(a) : "l"(p));
    return a;
}
__device__ __forceinline__ void cp_async16(uint32_t dst, const void* src) {
    asm volatile("cp.async.cg.shared.global [%0], [%1], 16;"
                 :: "r"(dst), "l"(src) : "memory");
}
__device__ __forceinline__ void cp_commit() {
    asm volatile("cp.async.commit_group;" ::: "memory");
}
template <int N>
__device__ __forceinline__ void cp_wait() {
    asm volatile("cp.async.wait_group %0;" :: "n"(N) : "memory");
}
__device__ __forceinline__ void mma16816(float* c, const uint32_t* a,
                                         const uint32_t* b) {
    asm volatile(
        "mma.sync.aligned.m16n8k16.row.col.f32.bf16.bf16.f32 "
        "{%0,%1,%2,%3}, {%4,%5,%6,%7}, {%8,%9}, {%0,%1,%2,%3};"
        : "+f"(c[0]), "+f"(c[1]), "+f"(c[2]), "+f"(c[3])
        : "r"(a[0]), "r"(a[1]), "r"(a[2]), "r"(a[3]), "r"(b[0]), "r"(b[1]));
}

// ---------------------------------------------------------------------------
// Kernel 1: per-episode class means -> g_M (fp32) + permuted split bf16
// ---------------------------------------------------------------------------
__global__ void __launch_bounds__(256) mean_kernel(const float* __restrict__ nf) {
    int b  = blockIdx.x;
    int f4 = threadIdx.x;                       // 0..255
    const float4* src = (const float4*)nf + (size_t)b * NN * (FD / 4);
    float4*        dst = (float4*)g_M    + (size_t)b * E6 * (FD / 4);
    __nv_bfloat16* dh  = g_Mh + (size_t)b * E6 * FD;
    __nv_bfloat16* dl  = g_Ml + (size_t)b * E6 * FD;

    const int k0   = f4 * 4;
    const int grp  = k0 & ~31;
    const int p01  = grp + pperm32(k0 & 31);        // pos of (k0, k0+1)
    const int p23  = grp + pperm32((k0 & 31) + 2);  // pos of (k0+2, k0+3)

    auto split4 = [&](size_t rowbase, float4 o) {
        __nv_bfloat162 h01, h23, l01, l23;
        h01.x = __float2bfloat16(o.x); h01.y = __float2bfloat16(o.y);
        h23.x = __float2bfloat16(o.z); h23.y = __float2bfloat16(o.w);
        l01.x = __float2bfloat16(o.x - __bfloat162float(h01.x));
        l01.y = __float2bfloat16(o.y - __bfloat162float(h01.y));
        l23.x = __float2bfloat16(o.z - __bfloat162float(h23.x));
        l23.y = __float2bfloat16(o.w - __bfloat162float(h23.y));
        *(__nv_bfloat162*)(dh + rowbase + p01) = h01;
        *(__nv_bfloat162*)(dh + rowbase + p23) = h23;
        *(__nv_bfloat162*)(dl + rowbase + p01) = l01;
        *(__nv_bfloat162*)(dl + rowbase + p23) = l23;
    };

#pragma unroll
    for (int c = 0; c < 5; c++) {
        float4 s0 = src[(c * 5 + 0) * (FD / 4) + f4];
        float4 s1 = src[(c * 5 + 1) * (FD / 4) + f4];
        float4 s2 = src[(c * 5 + 2) * (FD / 4) + f4];
        float4 s3 = src[(c * 5 + 3) * (FD / 4) + f4];
        float4 s4 = src[(c * 5 + 4) * (FD / 4) + f4];
        float4 o;
        o.x = (s0.x + s1.x + s2.x + s3.x + s4.x) / 5.0f;
        o.y = (s0.y + s1.y + s2.y + s3.y + s4.y) / 5.0f;
        o.z = (s0.z + s1.z + s2.z + s3.z + s4.z) / 5.0f;
        o.w = (s0.w + s1.w + s2.w + s3.w + s4.w) / 5.0f;
        dst[c * (FD / 4) + f4] = o;
        split4((size_t)c * FD, o);
    }
    float4 q = src[25 * (FD / 4) + f4];
    dst[5 * (FD / 4) + f4] = q;
    split4((size_t)5 * FD, q);
}

// ---------------------------------------------------------------------------
// Weight split: fp32 -> (hi, lo) bf16, 32-wide permuted k layout
// ---------------------------------------------------------------------------
__global__ void __launch_bounds__(256) split_kernel(const float* __restrict__ w,
                                                    __nv_bfloat16* __restrict__ hi,
                                                    __nv_bfloat16* __restrict__ lo,
                                                    int n, int K) {
    int i = blockIdx.x * blockDim.x + threadIdx.x;
    if (i < n) {
        int k   = i % K;
        int row = i / K;
        int pi  = row * K + (k & ~31) + pperm32(k & 31);
        float x = w[i];
        __nv_bfloat16 h = __float2bfloat16(x);
        hi[pi] = h;
        lo[pi] = __float2bfloat16(x - __bfloat162float(h));
    }
}

// ---------------------------------------------------------------------------
// 3-term split-bf16 HMMA GEMM:  acc += Ah*Wh + Al*Wh + Ah*Wl
// CTA tile 128x64, 128 threads = 4 warps (2x2), warp tile 64x32 (m16n8k16).
// BK=32, UNPADDED 64B-row tiles (consecutive rows tile 128B lines ->
// conflict-free LDS.128).  One LDS.128 per fragment covers both k16 halves
// (32-wide permuted layout).  smem = 2 x 24KB -> 3-4 CTAs/SM.
// Double-buffered, 1 sync per chunk (proven R14 loop structure).
// LAYER 1/2: bias+BN+leaky -> split bf16 (permuted).  LAYER 3: sigmoid^2 fp32.
// ---------------------------------------------------------------------------
#define ATILEB (128 * 64)              // 8192 B  (A hi or lo tile, 128 rows)
#define WTILEB (64 * 64)               // 4096 B  (W hi or lo tile, 64 rows)
#define BUFB   (2 * ATILEB + 2 * WTILEB)   // 24576 per stage
#define GEMM_SMEM_BYTES (2 * BUFB)     // 49152

template <int K, int NCOL, int LAYER>
__global__ void __launch_bounds__(128, 3) gemm_ps(
    const __nv_bfloat16* __restrict__ Ah,
    const __nv_bfloat16* __restrict__ Al,
    const __nv_bfloat16* __restrict__ Wh,
    const __nv_bfloat16* __restrict__ Wl,
    const float* __restrict__ bias,
    const float* __restrict__ gamma,
    const float* __restrict__ beta,
    const float* __restrict__ rmean,
    const float* __restrict__ rvar)
{
    extern __shared__ __align__(16) unsigned char sbuf[];

    constexpr int NCHUNK = K / 32;

    const int tid  = threadIdx.x;
    const int wid  = tid >> 5;
    const int lane = tid & 31;
    const int wrow = wid >> 1;           // 0..1 -> 64-row block
    const int wcol = wid & 1;            // 0..1 -> 32-col block
    const int g    = lane >> 2;          // 0..7
    const int tg   = lane & 3;           // 0..3
    const int row0 = blockIdx.x * 128;
    const int col0 = blockIdx.y * 64;

    // issue one 32-K chunk of all four operands into stage buffer `buf`
    //   segs: Ah 512, Al 512, Wh 256, Wl 256  = 1536 -> 12 per thread
    auto issue_chunk = [&](int kb, int buf) {
        const uint32_t base = smem_u32(sbuf) + (uint32_t)buf * BUFB;
#pragma unroll
        for (int i = 0; i < 12; i++) {
            const int idx = i * 128 + tid;            // 0..1535
            uint32_t dst; const __nv_bfloat16* src;
            if (idx < 1024) {                         // A tiles
                const int t = idx >> 9;               // 0=Ah 1=Al
                const int rem = idx & 511;
                const int r = rem >> 2, s = rem & 3;
                dst = base + t * ATILEB + r * 64 + s * 16;
                src = (t ? Al : Ah) + (size_t)(row0 + r) * K + kb + s * 8;
            } else {                                  // W tiles
                const int t = (idx - 1024) >> 8;      // 0=Wh 1=Wl
                const int rem = idx & 255;
                const int r = rem >> 2, s = rem & 3;
                dst = base + 2 * ATILEB + t * WTILEB + r * 64 + s * 16;
                src = (t ? Wl : Wh) + (size_t)(col0 + r) * K + kb + s * 8;
            }
            cp_async16(dst, src);
        }
        cp_commit();
    };

    float acc[4][4][4];
#pragma unroll
    for (int mt = 0; mt < 4; mt++)
#pragma unroll
        for (int nt = 0; nt < 4; nt++)
#pragma unroll
            for (int e = 0; e < 4; e++) acc[mt][nt][e] = 0.0f;

    issue_chunk(0, 0);

    for (int cc = 0; cc < NCHUNK; cc++) {
        const int buf = cc & 1;
        cp_wait<0>();
        __syncthreads();
        if (cc + 1 < NCHUNK) issue_chunk((cc + 1) * 32, buf ^ 1);

        const unsigned char* pA = sbuf + (size_t)buf * BUFB;
        const unsigned char* pAl = pA + ATILEB;
        const unsigned char* pWh = pA + 2 * ATILEB;
        const unsigned char* pWl = pWh + WTILEB;

        // ---- B fragments (both ks halves in one LDS.128), 4 n-tiles ----
        uint4 wbh[4], wbl[4];
#pragma unroll
        for (int nt = 0; nt < 4; nt++) {
            const int ro = (wcol * 32 + nt * 8 + g) * 64 + tg * 16;
            wbh[nt] = *(const uint4*)(pWh + ro);
            wbl[nt] = *(const uint4*)(pWl + ro);
        }
        // ---- per m-tile: 4 LDS.128 for A (hi/lo x rows g,g+8), then MMAs --
#pragma unroll
        for (int mt = 0; mt < 4; mt++) {
            const int ro = (wrow * 64 + mt * 16 + g) * 64 + tg * 16;
            uint4 h1 = *(const uint4*)(pA  + ro);            // hi, row g
            uint4 h2 = *(const uint4*)(pA  + ro + 8 * 64);   // hi, row g+8
            uint4 l1 = *(const uint4*)(pAl + ro);
            uint4 l2 = *(const uint4*)(pAl + ro + 8 * 64);
#pragma unroll
            for (int ks = 0; ks < 2; ks++) {
                uint32_t ah[4], al[4];
                if (ks == 0) {
                    ah[0] = h1.x; ah[1] = h2.x; ah[2] = h1.y; ah[3] = h2.y;
                    al[0] = l1.x; al[1] = l2.x; al[2] = l1.y; al[3] = l2.y;
                } else {
                    ah[0] = h1.z; ah[1] = h2.z; ah[2] = h1.w; ah[3] = h2.w;
                    al[0] = l1.z; al[1] = l2.z; al[2] = l1.w; al[3] = l2.w;
                }
#pragma unroll
                for (int nt = 0; nt < 4; nt++) {
                    uint32_t bh[2], bl[2];
                    if (ks == 0) {
                        bh[0] = wbh[nt].x; bh[1] = wbh[nt].y;
                        bl[0] = wbl[nt].x; bl[1] = wbl[nt].y;
                    } else {
                        bh[0] = wbh[nt].z; bh[1] = wbh[nt].w;
                        bl[0] = wbl[nt].z; bl[1] = wbl[nt].w;
                    }
                    mma16816(acc[mt][nt], ah, bh);
                    mma16816(acc[mt][nt], al, bh);
                    mma16816(acc[mt][nt], ah, bl);
                }
            }
        }
    }

    // -------- fused epilogue --------
    const int er0 = row0 + wrow * 64 + g;
    const int ec0 = col0 + wcol * 32 + 2 * tg;

#pragma unroll
    for (int nt = 0; nt < 4; nt++) {
        const int h0 = ec0 + nt * 8;
        float sc0, sh0 = 0.f, sc1, sh1 = 0.f;
        if (LAYER == 3) {
            sc0 = bias[h0]; sc1 = bias[h0 + 1];
        } else {
            float s0 = gamma[h0] * rsqrtf(rvar[h0] + 1e-5f);
            float s1 = gamma[h0 + 1] * rsqrtf(rvar[h0 + 1] + 1e-5f);
            sc0 = s0; sh0 = (bias[h0] - rmean[h0]) * s0 + beta[h0];
            sc1 = s1; sh1 = (bias[h0 + 1] - rmean[h0 + 1]) * s1 + beta[h0 + 1];
        }
        const int hperm = (h0 & ~31) + pperm32(h0 & 31);   // permuted pair pos
#pragma unroll
        for (int mt = 0; mt < 4; mt++) {
#pragma unroll
            for (int half = 0; half < 2; half++) {
                int r = er0 + mt * 16 + half * 8;
                float v0 = acc[mt][nt][half * 2 + 0];
                float v1 = acc[mt][nt][half * 2 + 1];
                if (LAYER == 3) {
                    float y0 = v0 + sc0, y1 = v1 + sc1;
                    float q0 = 1.0f / (1.0f + expf(-y0));
                    float q1 = 1.0f / (1.0f + expf(-y1));
                    float2 o; o.x = q0 * q0; o.y = q1 * q1;
                    *(float2*)(g_A2 + (size_t)r * NCOL + h0) = o;
                } else {
                    float y0 = v0 * sc0 + sh0;
                    float y1 = v1 * sc1 + sh1;
                    y0 = (y0 > 0.0f) ? y0 : 0.01f * y0;
                    y1 = (y1 > 0.0f) ? y1 : 0.01f * y1;
                    __nv_bfloat16* Ch = (LAYER == 1) ? g_Y1h : g_Y2h;
                    __nv_bfloat16* Cl = (LAYER == 1) ? g_Y1l : g_Y2l;
                    __nv_bfloat162 hp, lp;
                    hp.x = __float2bfloat16(y0);
                    hp.y = __float2bfloat16(y1);
                    lp.x = __float2bfloat16(y0 - __bfloat162float(hp.x));
                    lp.y = __float2bfloat16(y1 - __bfloat162float(hp.y));
                    *(__nv_bfloat162*)(Ch + (size_t)r * NCOL + hperm) = hp;
                    *(__nv_bfloat162*)(Cl + (size_t)r * NCOL + hperm) = lp;
                }
            }
        }
    }
}

// ---------------------------------------------------------------------------
// Kernel: per-episode 6x6 cosine similarity, ONE WARP PER EPISODE (proven).
// ---------------------------------------------------------------------------
__global__ void __launch_bounds__(256) sim_kernel(float* __restrict__ out) {
    const int tid  = threadIdx.x;
    const int wid  = tid >> 5;
    const int lane = tid & 31;
    const int ep   = blockIdx.x * 8 + wid;      // episode

    __shared__ float sred[8][57];
    __shared__ float ssim[8][36];

    const float* Mb = g_M  + (size_t)ep * E6 * FD;
    const float* Ab = g_A2 + (size_t)ep * E6 * FD;

    float d[21], n2[36];
#pragma unroll
    for (int t = 0; t < 21; t++) d[t] = 0.0f;
#pragma unroll
    for (int t = 0; t < 36; t++) n2[t] = 0.0f;

    for (int it = 0; it < FD / 32; it++) {
        const int f = lane + it * 32;
        float x[6], a[6];
#pragma unroll
        for (int i = 0; i < 6; i++) {
            x[i] = Mb[i * FD + f];
            a[i] = Ab[i * FD + f];
        }
        float p[6], q[6];
#pragma unroll
        for (int i = 0; i < 6; i++) {
            p[i] = a[i] * x[i];
            q[i] = p[i] * x[i];
        }
        {
            int t = 0;
#pragma unroll
            for (int i = 0; i < 6; i++)
#pragma unroll
                for (int j = i; j < 6; j++) { d[t] += p[i] * p[j]; t++; }
        }
#pragma unroll
        for (int i = 0; i < 6; i++)
#pragma unroll
            for (int j = 0; j < 6; j++)
                n2[i * 6 + j] += q[i] * a[j];
    }

    // warp butterfly reduce (all lanes end with the full sums)
#pragma unroll
    for (int off = 16; off > 0; off >>= 1) {
#pragma unroll
        for (int t = 0; t < 21; t++)
            d[t] += __shfl_xor_sync(0xffffffffu, d[t], off);
#pragma unroll
        for (int t = 0; t < 36; t++)
            n2[t] += __shfl_xor_sync(0xffffffffu, n2[t], off);
    }

    // scatter to smem with static register indexing
#pragma unroll
    for (int t = 0; t < 21; t++)
        if (lane == t) sred[wid][t] = d[t];
#pragma unroll
    for (int t = 0; t < 32; t++)
        if (lane == t) sred[wid][21 + t] = n2[t];
#pragma unroll
    for (int t = 32; t < 36; t++)
        if (lane == t - 32 + 8) sred[wid][21 + t] = n2[t];   // lanes 8..11
    __syncwarp();

    // all 36 ordered pairs (lanes 0..3 handle two pairs)
    for (int t = lane; t < 36; t += 32) {
        int i = t / 6, j = t % 6;
        int lo = i < j ? i : j;
        int hi = i < j ? j : i;
        int tidx = 6 * lo - (lo * (lo - 1)) / 2 + (hi - lo);
        float dd  = sred[wid][tidx];
        float nij = sred[wid][21 + i * 6 + j];
        float nji = sred[wid][21 + j * 6 + i];
        ssim[wid][t] = dd / (sqrtf(nij) * sqrtf(nji));
    }
    __syncwarp();

    size_t base = (size_t)ep * (2 * NN * NN);
    for (int idx = lane; idx < 2 * NN * NN; idx += 32) {
        int s  = idx / (NN * NN);
        int rr = idx - s * (NN * NN);
        int i  = rr / NN;
        int j  = rr - i * NN;
        int ci = (i < 25) ? (i / 5) : 5;
        int cj = (j < 25) ? (j / 5) : 5;
        float v = ssim[wid][ci * 6 + cj];
        if (s) v = 1.0f - v;
        out[base + idx] = fminf(fmaxf(v, 0.0f), 1.0f);
    }
}

// ---------------------------------------------------------------------------
// Launch (graph-capturable)
// ---------------------------------------------------------------------------
extern "C" void kernel_launch(void* const* d_in, const int* in_sizes, int n_in,
                              void* d_out, int out_size) {
    const float* nf  = (const float*)d_in[0];
    const float* w1  = (const float*)d_in[1];
    const float* b1  = (const float*)d_in[2];
    const float* g1  = (const float*)d_in[3];
    const float* be1 = (const float*)d_in[4];
    const float* m1  = (const float*)d_in[5];
    const float* v1  = (const float*)d_in[6];
    const float* w2  = (const float*)d_in[7];
    const float* b2  = (const float*)d_in[8];
    const float* g2  = (const float*)d_in[9];
    const float* be2 = (const float*)d_in[10];
    const float* m2  = (const float*)d_in[11];
    const float* v2  = (const float*)d_in[12];
    const float* w3  = (const float*)d_in[13];
    const float* b3  = (const float*)d_in[14];
    float* out = (float*)d_out;

    __nv_bfloat16 *pMh, *pMl, *pY1h, *pY1l, *pY2h, *pY2l;
    __nv_bfloat16 *pW1h, *pW1l, *pW2h, *pW2l, *pW3h, *pW3l;
    cudaGetSymbolAddress((void**)&pMh,  g_Mh);
    cudaGetSymbolAddress((void**)&pMl,  g_Ml);
    cudaGetSymbolAddress((void**)&pY1h, g_Y1h);
    cudaGetSymbolAddress((void**)&pY1l, g_Y1l);
    cudaGetSymbolAddress((void**)&pY2h, g_Y2h);
    cudaGetSymbolAddress((void**)&pY2l, g_Y2l);
    cudaGetSymbolAddress((void**)&pW1h, g_W1h);
    cudaGetSymbolAddress((void**)&pW1l, g_W1l);
    cudaGetSymbolAddress((void**)&pW2h, g_W2h);
    cudaGetSymbolAddress((void**)&pW2l, g_W2l);
    cudaGetSymbolAddress((void**)&pW3h, g_W3h);
    cudaGetSymbolAddress((void**)&pW3l, g_W3l);

    cudaFuncSetAttribute(gemm_ps<FD, HD, 1>,
                         cudaFuncAttributeMaxDynamicSharedMemorySize,
                         GEMM_SMEM_BYTES);
    cudaFuncSetAttribute(gemm_ps<HD, HD, 2>,
                         cudaFuncAttributeMaxDynamicSharedMemorySize,
                         GEMM_SMEM_BYTES);
    cudaFuncSetAttribute(gemm_ps<HD, FD, 3>,
                         cudaFuncAttributeMaxDynamicSharedMemorySize,
                         GEMM_SMEM_BYTES);

    // weight splits (fp32 -> hi/lo bf16, permuted layout)
    split_kernel<<<(HD * FD + 255) / 256, 256>>>(w1, pW1h, pW1l, HD * FD, FD);
    split_kernel<<<(HD * HD + 255) / 256, 256>>>(w2, pW2h, pW2l, HD * HD, HD);
    split_kernel<<<(FD * HD + 255) / 256, 256>>>(w3, pW3h, pW3l, FD * HD, HD);

    // class means (fp32 + permuted split bf16)
    mean_kernel<<<NB, 256>>>(nf);

    // Y1 = leaky(bn1(M @ w1^T + b1))
    gemm_ps<FD, HD, 1><<<dim3(ET / 128, HD / 64), 128, GEMM_SMEM_BYTES>>>(
        pMh, pMl, pW1h, pW1l, b1, g1, be1, m1, v1);
    // Y2 = leaky(bn2(Y1 @ w2^T + b2))
    gemm_ps<HD, HD, 2><<<dim3(ET / 128, HD / 64), 128, GEMM_SMEM_BYTES>>>(
        pY1h, pY1l, pW2h, pW2l, b2, g2, be2, m2, v2);
    // A2 = sigmoid(Y2 @ w3^T + b3)^2
    gemm_ps<HD, FD, 3><<<dim3(ET / 128, FD / 64), 128, GEMM_SMEM_BYTES>>>(
        pY2h, pY2l, pW3h, pW3l, b3, nullptr, nullptr, nullptr, nullptr);

    // per-episode 6x6 cosine sim -> broadcast [2,26,26]  (one warp/episode)
    sim_kernel<<<NB / 8, 256>>>(out);
}